// round 2
// baseline (speedup 1.0000x reference)
#include <cuda_runtime.h>
#include <cstdint>

// N-body all-pairs gravity, fp32, using packed f32x2 math (sm_103a FFMA2 path).
// Two j-bodies are packed per 64-bit register pair; shared memory holds the
// tile in pre-paired SoA so LDS.64 delivers packed operands directly.

constexpr int NBODY  = 8192;
constexpr int BLOCK  = 128;
constexpr int NSPLIT = 16;                // grid 64 x 16 = 1024 CTAs
constexpr int CHUNK  = NBODY / NSPLIT;    // 512 j-bodies per tile
constexpr int PAIRS  = CHUNK / 2;         // 256 packed pairs

// ---- packed f32x2 helpers (Blackwell-only; ptxas never auto-emits these) ----
__device__ __forceinline__ uint64_t pk2(float lo, float hi) {
    uint64_t r; asm("mov.b64 %0, {%1, %2};" : "=l"(r) : "f"(lo), "f"(hi)); return r;
}
__device__ __forceinline__ void upk2(uint64_t v, float& lo, float& hi) {
    asm("mov.b64 {%0, %1}, %2;" : "=f"(lo), "=f"(hi) : "l"(v));
}
__device__ __forceinline__ uint64_t add2(uint64_t a, uint64_t b) {
    uint64_t r; asm("add.rn.f32x2 %0, %1, %2;" : "=l"(r) : "l"(a), "l"(b)); return r;
}
__device__ __forceinline__ uint64_t mul2(uint64_t a, uint64_t b) {
    uint64_t r; asm("mul.rn.f32x2 %0, %1, %2;" : "=l"(r) : "l"(a), "l"(b)); return r;
}
__device__ __forceinline__ uint64_t fma2(uint64_t a, uint64_t b, uint64_t c) {
    uint64_t r; asm("fma.rn.f32x2 %0, %1, %2, %3;" : "=l"(r) : "l"(a), "l"(b), "l"(c)); return r;
}

__global__ __launch_bounds__(BLOCK)
void nbody_kernel(const float* __restrict__ pos,
                  const float* __restrict__ mass,
                  float* __restrict__ out)
{
    // Pre-paired SoA: element p holds bodies (2p, 2p+1) of this tile.
    __shared__ float2 shX[PAIRS];
    __shared__ float2 shY[PAIRS];
    __shared__ float2 shZ[PAIRS];
    __shared__ float2 shM[PAIRS];

    const int i     = blockIdx.x * BLOCK + threadIdx.x;
    const int jBase = blockIdx.y * CHUNK;

    for (int p = threadIdx.x; p < PAIRS; p += BLOCK) {
        const int j0 = jBase + 2 * p;
        const int j1 = j0 + 1;
        shX[p] = make_float2(pos[3 * j0 + 0], pos[3 * j1 + 0]);
        shY[p] = make_float2(pos[3 * j0 + 1], pos[3 * j1 + 1]);
        shZ[p] = make_float2(pos[3 * j0 + 2], pos[3 * j1 + 2]);
        shM[p] = make_float2(mass[j0],        mass[j1]);
    }
    __syncthreads();

    const float px = pos[3 * i + 0];
    const float py = pos[3 * i + 1];
    const float pz = pos[3 * i + 2];

    const uint64_t npx  = pk2(-px, -px);
    const uint64_t npy  = pk2(-py, -py);
    const uint64_t npz  = pk2(-pz, -pz);
    const uint64_t eps2 = pk2(1e-4f, 1e-4f);   // softening^2

    uint64_t FX = pk2(0.f, 0.f);
    uint64_t FY = pk2(0.f, 0.f);
    uint64_t FZ = pk2(0.f, 0.f);

    const uint64_t* __restrict__ sx = reinterpret_cast<const uint64_t*>(shX);
    const uint64_t* __restrict__ sy = reinterpret_cast<const uint64_t*>(shY);
    const uint64_t* __restrict__ sz = reinterpret_cast<const uint64_t*>(shZ);
    const uint64_t* __restrict__ sm = reinterpret_cast<const uint64_t*>(shM);

#pragma unroll 8
    for (int p = 0; p < PAIRS; ++p) {
        const uint64_t X = sx[p];   // LDS.64 broadcast — already packed
        const uint64_t Y = sy[p];
        const uint64_t Z = sz[p];
        const uint64_t M = sm[p];

        const uint64_t dx = add2(X, npx);
        const uint64_t dy = add2(Y, npy);
        const uint64_t dz = add2(Z, npz);
        const uint64_t d2 = fma2(dx, dx, fma2(dy, dy, fma2(dz, dz, eps2)));

        float d2lo, d2hi;
        upk2(d2, d2lo, d2hi);
        const uint64_t R  = pk2(rsqrtf(d2lo), rsqrtf(d2hi));  // 2x MUFU.RSQ
        const uint64_t R2 = mul2(R, R);
        const uint64_t R3 = mul2(R2, R);
        const uint64_t W  = mul2(R3, M);                      // m_j * d^-1.5

        FX = fma2(W, dx, FX);
        FY = fma2(W, dy, FY);
        FZ = fma2(W, dz, FZ);
    }

    float a, b;
    upk2(FX, a, b); atomicAdd(&out[3 * i + 0], a + b);
    upk2(FY, a, b); atomicAdd(&out[3 * i + 1], a + b);
    upk2(FZ, a, b); atomicAdd(&out[3 * i + 2], a + b);
}

extern "C" void kernel_launch(void* const* d_in, const int* in_sizes, int n_in,
                              void* d_out, int out_size)
{
    const float* pos  = (const float*)d_in[0];
    const float* mass = (const float*)d_in[1];
    float*       out  = (float*)d_out;

    cudaMemsetAsync(out, 0, (size_t)out_size * sizeof(float));

    dim3 grid(NBODY / BLOCK, NSPLIT);
    nbody_kernel<<<grid, BLOCK>>>(pos, mass, out);
}

// round 3
// speedup vs baseline: 1.7920x; 1.7920x over previous
#include <cuda_runtime.h>

// N-body all-pairs gravity forces, fp32 scalar path (R1 inner loop),
// with occupancy fixed: 1024 CTAs x 256 threads (~86% occ) instead of
// 512 x 128 (~21% occ, launch-limited -> issue stalls).

constexpr int NBODY  = 8192;
constexpr int BLOCK  = 256;               // one body i per thread
constexpr int NSPLIT = 32;                // j-dimension splits
constexpr int CHUNK  = NBODY / NSPLIT;    // 256 j-bodies per tile (4 KB smem)

__global__ __launch_bounds__(BLOCK)
void nbody_kernel(const float* __restrict__ pos,
                  const float* __restrict__ mass,
                  float* __restrict__ out)
{
    __shared__ float4 sh[CHUNK];

    const int i     = blockIdx.x * BLOCK + threadIdx.x;
    const int jBase = blockIdx.y * CHUNK;

    // Tile load: one float4 (x, y, z, m) per thread.
    {
        const int t = threadIdx.x;           // BLOCK == CHUNK
        const int j = jBase + t;
        sh[t] = make_float4(pos[3 * j + 0], pos[3 * j + 1], pos[3 * j + 2], mass[j]);
    }
    __syncthreads();

    const float px = pos[3 * i + 0];
    const float py = pos[3 * i + 1];
    const float pz = pos[3 * i + 2];

    float fx = 0.0f, fy = 0.0f, fz = 0.0f;

#pragma unroll 16
    for (int t = 0; t < CHUNK; ++t) {
        const float4 b = sh[t];              // LDS.128 broadcast, conflict-free
        const float dx = b.x - px;
        const float dy = b.y - py;
        const float dz = b.z - pz;
        // softening^2 = 1e-4 folded into the fma chain; j == i contributes 0.
        const float d2 = fmaf(dx, dx, fmaf(dy, dy, fmaf(dz, dz, 1e-4f)));
        const float r  = rsqrtf(d2);         // MUFU.RSQ
        const float w  = b.w * r * r * r;    // m_j * d^-1.5
        fx = fmaf(w, dx, fx);
        fy = fmaf(w, dy, fy);
        fz = fmaf(w, dz, fz);
    }

    // 32 partial contributions per output element; spread-address REDG.
    atomicAdd(&out[3 * i + 0], fx);
    atomicAdd(&out[3 * i + 1], fy);
    atomicAdd(&out[3 * i + 2], fz);
}

extern "C" void kernel_launch(void* const* d_in, const int* in_sizes, int n_in,
                              void* d_out, int out_size)
{
    const float* pos  = (const float*)d_in[0];   // [8192, 3] fp32
    const float* mass = (const float*)d_in[1];   // [8192]    fp32
    float*       out  = (float*)d_out;           // [8192, 3] fp32

    cudaMemsetAsync(out, 0, (size_t)out_size * sizeof(float));

    dim3 grid(NBODY / BLOCK, NSPLIT);
    nbody_kernel<<<grid, BLOCK>>>(pos, mass, out);
}

// round 4
// speedup vs baseline: 1.8031x; 1.0062x over previous
#include <cuda_runtime.h>

// N-body all-pairs gravity forces, fp32, i-register-blocked (IBLK=2).
// Each thread accumulates forces for TWO i-bodies against the shared j-tile:
// amortizes LDS + loop overhead and provides two independent MUFU.RSQ
// dependency chains per thread (issue-slot utilization was the R3 limiter).

constexpr int NBODY  = 8192;
constexpr int BLOCK  = 256;
constexpr int IBLK   = 2;
constexpr int IHALF  = NBODY / IBLK;          // 4096
constexpr int NSPLIT = 64;                    // j-dimension splits
constexpr int CHUNK  = NBODY / NSPLIT;        // 128 j-bodies per tile (2 KB)

__global__ __launch_bounds__(BLOCK)
void nbody_kernel(const float* __restrict__ pos,
                  const float* __restrict__ mass,
                  float* __restrict__ out)
{
    __shared__ float4 sh[CHUNK];

    const int i0    = blockIdx.x * BLOCK + threadIdx.x;   // [0, 4096)
    const int i1    = i0 + IHALF;                          // [4096, 8192)
    const int jBase = blockIdx.y * CHUNK;

    // Tile load (first CHUNK threads).
    if (threadIdx.x < CHUNK) {
        const int j = jBase + threadIdx.x;
        sh[threadIdx.x] = make_float4(pos[3 * j + 0], pos[3 * j + 1],
                                      pos[3 * j + 2], mass[j]);
    }
    __syncthreads();

    const float px0 = pos[3 * i0 + 0], py0 = pos[3 * i0 + 1], pz0 = pos[3 * i0 + 2];
    const float px1 = pos[3 * i1 + 0], py1 = pos[3 * i1 + 1], pz1 = pos[3 * i1 + 2];

    float fx0 = 0.f, fy0 = 0.f, fz0 = 0.f;
    float fx1 = 0.f, fy1 = 0.f, fz1 = 0.f;

#pragma unroll 16
    for (int t = 0; t < CHUNK; ++t) {
        const float4 b = sh[t];               // one LDS.128 serves both i-bodies

        // chain 0
        const float dx0 = b.x - px0;
        const float dy0 = b.y - py0;
        const float dz0 = b.z - pz0;
        const float d20 = fmaf(dx0, dx0, fmaf(dy0, dy0, fmaf(dz0, dz0, 1e-4f)));
        // chain 1 (independent)
        const float dx1 = b.x - px1;
        const float dy1 = b.y - py1;
        const float dz1 = b.z - pz1;
        const float d21 = fmaf(dx1, dx1, fmaf(dy1, dy1, fmaf(dz1, dz1, 1e-4f)));

        const float r0 = rsqrtf(d20);         // 2 overlapping MUFU.RSQ
        const float r1 = rsqrtf(d21);

        const float w0 = b.w * r0 * r0 * r0;
        const float w1 = b.w * r1 * r1 * r1;

        fx0 = fmaf(w0, dx0, fx0);
        fy0 = fmaf(w0, dy0, fy0);
        fz0 = fmaf(w0, dz0, fz0);
        fx1 = fmaf(w1, dx1, fx1);
        fy1 = fmaf(w1, dy1, fy1);
        fz1 = fmaf(w1, dz1, fz1);
    }

    atomicAdd(&out[3 * i0 + 0], fx0);
    atomicAdd(&out[3 * i0 + 1], fy0);
    atomicAdd(&out[3 * i0 + 2], fz0);
    atomicAdd(&out[3 * i1 + 0], fx1);
    atomicAdd(&out[3 * i1 + 1], fy1);
    atomicAdd(&out[3 * i1 + 2], fz1);
}

extern "C" void kernel_launch(void* const* d_in, const int* in_sizes, int n_in,
                              void* d_out, int out_size)
{
    const float* pos  = (const float*)d_in[0];   // [8192, 3] fp32
    const float* mass = (const float*)d_in[1];   // [8192]    fp32
    float*       out  = (float*)d_out;           // [8192, 3] fp32

    cudaMemsetAsync(out, 0, (size_t)out_size * sizeof(float));

    dim3 grid(IHALF / BLOCK, NSPLIT);            // 16 x 64 = 1024 CTAs
    nbody_kernel<<<grid, BLOCK>>>(pos, mass, out);
}